// round 1
// baseline (speedup 1.0000x reference)
#include <cuda_runtime.h>
#include <math.h>

#define BB   512
#define LL   256
#define DIN  384
#define DD   300
#define NS   13
#define NL   8
#define EPSL 1e-5f

#define KEP  4224                       // 13*300 + 300 = 4200, padded to x16 (and x64)
#define C_OFF 0
#define MEM_OFF   (BB*DIN)              // 196608
#define MEM_SIZE  (BB*NS*NL*DD)         // 15974400
#define LOGIT_OFF (MEM_OFF + MEM_SIZE)  // 16171008

// ---------- device scratch (static, allocation-free) ----------
__device__ float g_M[DIN*DD];           // fused in_W @ Wh0
__device__ float g_b0[DD];              // in_b @ Wh0 + lb0
__device__ float g_U[LL*BB*DD];         // U[t][b][j] = x[b,t] @ Wh0 + lb0   (157 MB)
__device__ float g_x0[BB*DD];
__device__ float g_sum[2][BB*DD];       // double-buffered slot-sum
__device__ float g_Aep[BB*KEP];
__device__ float g_Wep[KEP*DIN];
__device__ float g_c[BB*DIN];           // pre-LN c

// ---------- misc ----------
__global__ void k_zero_out(float* p, int n) {
    int i = blockIdx.x * blockDim.x + threadIdx.x;
    if (i < n) p[i] = 0.f;
}
__global__ void k_zero_sum() {
    int i = blockIdx.x * blockDim.x + threadIdx.x;
    if (i < BB*DD) g_sum[0][i] = 0.f;
}

// ---------- prep: g_M = in_W @ Wh0 ; g_b0 = in_b @ Wh0 + lb0 ----------
__global__ void k_prep_M(const float* __restrict__ in_W, const float* __restrict__ in_b,
                         const float* __restrict__ Wh0, const float* __restrict__ lb0) {
    __shared__ float row[DD];
    int di = blockIdx.x;                       // 0..384 (384 == bias row)
    const float* src = (di < DIN) ? (in_W + di*DD) : in_b;
    for (int k = threadIdx.x; k < DD; k += blockDim.x) row[k] = src[k];
    __syncthreads();
    for (int j = threadIdx.x; j < DD; j += blockDim.x) {
        float acc = 0.f;
        for (int k = 0; k < DD; k++) acc += row[k] * Wh0[k*DD + j];
        if (di < DIN) g_M[di*DD + j] = acc;
        else          g_b0[j] = acc + lb0[j];
    }
}

// ---------- prep: x0 = we[:,0,:] @ in_W + in_b ----------
__global__ void k_x0(const float* __restrict__ we, const float* __restrict__ in_W,
                     const float* __restrict__ in_b) {
    __shared__ float row[DIN];
    int b = blockIdx.x;
    for (int k = threadIdx.x; k < DIN; k += blockDim.x) row[k] = we[b*(LL*DIN) + k];
    __syncthreads();
    for (int j = threadIdx.x; j < DD; j += blockDim.x) {
        float acc = in_b[j];
        for (int k = 0; k < DIN; k++) acc += row[k] * in_W[k*DD + j];
        g_x0[b*DD + j] = acc;
    }
}

// ---------- U GEMM: U[t][b][:] = we[b,t,:] @ g_M + g_b0   (131072 x 300, K=384) ----------
// 64x64 tile, BK=16, 256 threads, 4x4 micro. Row rr = t*512 + b.
__global__ __launch_bounds__(256) void k_ugemm(const float* __restrict__ we) {
    __shared__ float As[16*68];   // As[kk][m], stride 68 (pad, 16B-aligned rows)
    __shared__ float Bs[16*64];   // Bs[kk][n]
    int bn = blockIdx.x;          // 0..4
    int bm = blockIdx.y;          // 0..2047
    int tid = threadIdx.x;
    int tr = tid >> 4, tc = tid & 15;
    int row0 = bm * 64, col0 = bn * 64;
    float acc[4][4] = {};
    for (int k0 = 0; k0 < DIN; k0 += 16) {
        for (int i = tid; i < 64*16; i += 256) {
            int kk = i & 15, m = i >> 4;
            int rr = row0 + m;
            int t = rr >> 9, b = rr & 511;
            As[kk*68 + m] = we[b*(LL*DIN) + t*DIN + k0 + kk];
        }
        for (int i = tid; i < 16*64; i += 256) {
            int n = i & 63, kk = i >> 6;
            int c = col0 + n;
            Bs[kk*64 + n] = (c < DD) ? g_M[(k0+kk)*DD + c] : 0.f;
        }
        __syncthreads();
        #pragma unroll
        for (int kk = 0; kk < 16; kk++) {
            float4 a = *(const float4*)&As[kk*68 + tr*4];
            float4 bv = *(const float4*)&Bs[kk*64 + tc*4];
            float av[4] = {a.x, a.y, a.z, a.w};
            float bvv[4] = {bv.x, bv.y, bv.z, bv.w};
            #pragma unroll
            for (int i = 0; i < 4; i++)
                #pragma unroll
                for (int j = 0; j < 4; j++) acc[i][j] += av[i] * bvv[j];
        }
        __syncthreads();
    }
    #pragma unroll
    for (int i = 0; i < 4; i++) {
        int rr = row0 + tr*4 + i;
        #pragma unroll
        for (int j = 0; j < 4; j++) {
            int c = col0 + tc*4 + j;
            if (c < DD) g_U[rr*DD + c] = acc[i][j] + g_b0[c];
        }
    }
}

// ---------- recurrence step: h = tanh(U_t + (sum @ Wr0)/13); mem/sum update ----------
// C[512,300] = sumIn @ Wr0 ; 32x32 tile, BK=32, 256 threads, 2x2 micro.
__global__ __launch_bounds__(256) void k_step(const float* __restrict__ Wr0,
                                              float* __restrict__ memo, int t) {
    __shared__ float As[32*33];   // As[kk][m]
    __shared__ float Bs[32*33];   // Bs[kk][n]
    const float* __restrict__ sumIn = g_sum[t & 1];
    float* __restrict__ sumOut = g_sum[(t & 1) ^ 1];
    int bn = blockIdx.x;          // 0..9
    int bm = blockIdx.y;          // 0..15
    int tid = threadIdx.x;
    int tr = tid >> 4, tc = tid & 15;
    int row0 = bm * 32, col0 = bn * 32;
    float acc[2][2] = {};
    for (int k0 = 0; k0 < DD; k0 += 32) {
        for (int i = tid; i < 1024; i += 256) {
            int kk = i & 31, m = i >> 5;
            int k = k0 + kk;
            As[kk*33 + m] = (k < DD) ? sumIn[(row0+m)*DD + k] : 0.f;
        }
        for (int i = tid; i < 1024; i += 256) {
            int n = i & 31, kk = i >> 5;
            int k = k0 + kk, c = col0 + n;
            Bs[kk*33 + n] = (k < DD && c < DD) ? Wr0[k*DD + c] : 0.f;
        }
        __syncthreads();
        #pragma unroll
        for (int kk = 0; kk < 32; kk++) {
            float a0 = As[kk*33 + tr*2], a1 = As[kk*33 + tr*2 + 1];
            float b0 = Bs[kk*33 + tc*2], b1 = Bs[kk*33 + tc*2 + 1];
            acc[0][0] += a0*b0; acc[0][1] += a0*b1;
            acc[1][0] += a1*b0; acc[1][1] += a1*b1;
        }
        __syncthreads();
    }
    int slot = t % NS;
    const float inv13 = 1.f / 13.f;
    const float* Ut = g_U + t*(BB*DD);
    #pragma unroll
    for (int i = 0; i < 2; i++) {
        int b = row0 + tr*2 + i;
        #pragma unroll
        for (int j = 0; j < 2; j++) {
            int c = col0 + tc*2 + j;
            if (c < DD) {
                float h = tanhf(Ut[b*DD + c] + acc[i][j] * inv13);
                int mi = b*(NS*NL*DD) + slot*(NL*DD) + c;   // layer 0
                float old = (t >= NS) ? memo[mi] : 0.f;
                memo[mi] = h;
                sumOut[b*DD + c] = sumIn[b*DD + c] + h - old;
            }
        }
    }
}

// ---------- epilogue gathers ----------
__global__ void k_gatherA(const float* __restrict__ memo) {
    int idx = blockIdx.x * blockDim.x + threadIdx.x;
    if (idx >= BB*KEP) return;
    int b = idx / KEP, k = idx % KEP;
    float v = 0.f;
    if (k < NS*DD)            { int s = k / DD, j = k % DD; v = memo[b*(NS*NL*DD) + s*(NL*DD) + j]; }
    else if (k < NS*DD + DD)  { v = g_x0[b*DD + (k - NS*DD)]; }
    g_Aep[idx] = v;
}
__global__ void k_gatherW(const float* __restrict__ out_W, const float* __restrict__ skip_W) {
    int idx = blockIdx.x * blockDim.x + threadIdx.x;
    if (idx >= KEP*DIN) return;
    int k = idx / DIN, o = idx % DIN;
    float v = 0.f;
    if (k < NS*DD)            { int s = k / DD, j = k % DD; v = out_W[(s*(NL*DD) + j)*DIN + o]; }
    else if (k < NS*DD + DD)  { v = skip_W[(k - NS*DD)*DIN + o]; }
    g_Wep[idx] = v;
}

// ---------- epilogue GEMM: g_c = g_Aep @ g_Wep + (out_b + skip_b) ----------
__global__ __launch_bounds__(256) void k_epigemm(const float* __restrict__ out_b,
                                                 const float* __restrict__ skip_b) {
    __shared__ float As[16*68];
    __shared__ float Bs[16*64];
    int bn = blockIdx.x;   // 0..5  (N=384)
    int bm = blockIdx.y;   // 0..7  (M=512)
    int tid = threadIdx.x;
    int tr = tid >> 4, tc = tid & 15;
    int row0 = bm * 64, col0 = bn * 64;
    float acc[4][4] = {};
    for (int k0 = 0; k0 < KEP; k0 += 16) {
        for (int i = tid; i < 64*16; i += 256) {
            int kk = i & 15, m = i >> 4;
            As[kk*68 + m] = g_Aep[(row0+m)*KEP + k0 + kk];
        }
        for (int i = tid; i < 16*64; i += 256) {
            int n = i & 63, kk = i >> 6;
            Bs[kk*64 + n] = g_Wep[(k0+kk)*DIN + col0 + n];
        }
        __syncthreads();
        #pragma unroll
        for (int kk = 0; kk < 16; kk++) {
            float4 a = *(const float4*)&As[kk*68 + tr*4];
            float4 bv = *(const float4*)&Bs[kk*64 + tc*4];
            float av[4] = {a.x, a.y, a.z, a.w};
            float bvv[4] = {bv.x, bv.y, bv.z, bv.w};
            #pragma unroll
            for (int i = 0; i < 4; i++)
                #pragma unroll
                for (int j = 0; j < 4; j++) acc[i][j] += av[i] * bvv[j];
        }
        __syncthreads();
    }
    #pragma unroll
    for (int i = 0; i < 4; i++) {
        int rr = row0 + tr*4 + i;
        #pragma unroll
        for (int j = 0; j < 4; j++) {
            int c = col0 + tc*4 + j;
            g_c[rr*DIN + c] = acc[i][j] + out_b[c] + skip_b[c];
        }
    }
}

// ---------- LayerNorm ----------
__device__ __forceinline__ float blk_reduce(float v, float* sm) {
    int lane = threadIdx.x & 31, w = threadIdx.x >> 5;
    #pragma unroll
    for (int o = 16; o > 0; o >>= 1) v += __shfl_xor_sync(0xffffffff, v, o);
    if (lane == 0) sm[w] = v;
    __syncthreads();
    v = (threadIdx.x < 4) ? sm[threadIdx.x] : 0.f;
    if (threadIdx.x < 4) {
        #pragma unroll
        for (int o = 2; o > 0; o >>= 1) v += __shfl_xor_sync(0xf, v, o);
        if (threadIdx.x == 0) sm[0] = v;
    }
    __syncthreads();
    return sm[0];
}
__global__ __launch_bounds__(128) void k_ln(const float* __restrict__ g,
                                            const float* __restrict__ be,
                                            float* __restrict__ out) {
    __shared__ float sm[4];
    int b = blockIdx.x, tid = threadIdx.x;
    float v[3];
    float s = 0.f;
    #pragma unroll
    for (int r = 0; r < 3; r++) { v[r] = g_c[b*DIN + tid + r*128]; s += v[r]; }
    float mu = blk_reduce(s, sm) * (1.f / DIN);
    __syncthreads();
    float q = 0.f;
    #pragma unroll
    for (int r = 0; r < 3; r++) { float d = v[r] - mu; q += d * d; }
    float var = blk_reduce(q, sm) * (1.f / DIN);
    float rs = rsqrtf(var + EPSL);
    #pragma unroll
    for (int r = 0; r < 3; r++) {
        int i = tid + r*128;
        out[C_OFF + b*DIN + i] = (v[r] - mu) * rs * g[i] + be[i];
    }
}

// ---------- scoring head ----------
__global__ __launch_bounds__(64) void k_logit(const float* __restrict__ W1,
                                              const float* __restrict__ b1,
                                              const float* __restrict__ W2,
                                              const float* __restrict__ b2,
                                              float* __restrict__ out) {
    __shared__ float cs[DIN];
    __shared__ float red[2];
    int b = blockIdx.x, tid = threadIdx.x;
    for (int i = tid; i < DIN; i += 64) cs[i] = out[C_OFF + b*DIN + i];
    __syncthreads();
    float acc = b1[tid];
    for (int i = 0; i < DIN; i++) acc += cs[i] * W1[i*64 + tid];
    float r = fmaxf(acc, 0.f) * W2[tid];
    #pragma unroll
    for (int o = 16; o > 0; o >>= 1) r += __shfl_xor_sync(0xffffffff, r, o);
    if ((tid & 31) == 0) red[tid >> 5] = r;
    __syncthreads();
    if (tid == 0) out[LOGIT_OFF + b] = red[0] + red[1] + b2[0];
}

// ---------- launcher ----------
extern "C" void kernel_launch(void* const* d_in, const int* in_sizes, int n_in,
                              void* d_out, int out_size) {
    const float* we     = (const float*)d_in[0];
    const float* in_W   = (const float*)d_in[1];
    const float* in_b   = (const float*)d_in[2];
    const float* Wh     = (const float*)d_in[3];   // Wh0 = first 300*300
    const float* Wr     = (const float*)d_in[4];   // Wr0 = first 300*300
    const float* lb     = (const float*)d_in[5];   // lb0 = first 300
    const float* skip_W = (const float*)d_in[6];
    const float* skip_b = (const float*)d_in[7];
    const float* out_W  = (const float*)d_in[8];
    const float* out_b  = (const float*)d_in[9];
    const float* ln_g   = (const float*)d_in[10];
    const float* ln_b   = (const float*)d_in[11];
    const float* sh_W1  = (const float*)d_in[12];
    const float* sh_b1  = (const float*)d_in[13];
    const float* sh_W2  = (const float*)d_in[14];
    const float* sh_b2  = (const float*)d_in[15];
    float* out = (float*)d_out;
    float* memo = out + MEM_OFF;

    // init
    k_zero_out<<<(MEM_SIZE + 255) / 256, 256>>>(memo, MEM_SIZE);
    k_zero_sum<<<(BB*DD + 255) / 256, 256>>>();

    // prep
    k_prep_M<<<DIN + 1, 128>>>(in_W, in_b, Wh, lb);
    k_x0<<<BB, 128>>>(we, in_W, in_b);

    // parallel input projection: U[t][b][:] for all t
    k_ugemm<<<dim3(5, 2048), 256>>>(we);

    // sequential recurrence (layer 0 only; layers 1..7 are dead code in the reference)
    for (int t = 0; t < LL; t++)
        k_step<<<dim3(10, 16), 256>>>(Wr, memo, t);

    // epilogue
    k_gatherA<<<(BB*KEP + 255) / 256, 256>>>(memo);
    k_gatherW<<<(KEP*DIN + 255) / 256, 256>>>(out_W, skip_W);
    k_epigemm<<<dim3(6, 8), 256>>>(out_b, skip_b);
    k_ln<<<BB, 128>>>(ln_g, ln_b, out);
    k_logit<<<BB, 64>>>(sh_W1, sh_b1, sh_W2, sh_b2, out);
}

// round 2
// speedup vs baseline: 2.0762x; 2.0762x over previous
#include <cuda_runtime.h>
#include <math.h>

#define BB   512
#define LL   256
#define DIN  384
#define DD   300
#define NS   13
#define NL   8
#define EPSL 1e-5f

#define KEP  4224                       // 13*300 + 300 = 4200, padded
#define C_OFF 0
#define MEM_OFF   (BB*DIN)              // 196608
#define MEM_SIZE  (BB*NS*NL*DD)         // 15974400
#define LOGIT_OFF (MEM_OFF + MEM_SIZE)  // 16171008

#define RROWS  4                        // batch rows per recurrence block
#define SUMSTR 304                      // padded row stride (16B aligned)

// ---------- device scratch (static, allocation-free) ----------
__device__ float g_M[DIN*DD];           // fused in_W @ Wh0
__device__ float g_b0[DD];              // in_b @ Wh0 + lb0
__device__ float g_U[(size_t)LL*BB*DD]; // U[t][b][j]
__device__ float g_x0[BB*DD];
__device__ float g_Aep[BB*KEP];
__device__ float g_Wep[KEP*DIN];
__device__ float g_c[BB*DIN];           // pre-LN c

// ---------- misc ----------
__global__ void k_zero_out(float* p, int n) {
    int i = blockIdx.x * blockDim.x + threadIdx.x;
    if (i < n) p[i] = 0.f;
}

// ---------- prep: g_M = in_W @ Wh0 ; g_b0 = in_b @ Wh0 + lb0 ----------
__global__ void k_prep_M(const float* __restrict__ in_W, const float* __restrict__ in_b,
                         const float* __restrict__ Wh0, const float* __restrict__ lb0) {
    __shared__ float row[DD];
    int di = blockIdx.x;                       // 0..384 (384 == bias row)
    const float* src = (di < DIN) ? (in_W + di*DD) : in_b;
    for (int k = threadIdx.x; k < DD; k += blockDim.x) row[k] = src[k];
    __syncthreads();
    for (int j = threadIdx.x; j < DD; j += blockDim.x) {
        float acc = 0.f;
        for (int k = 0; k < DD; k++) acc += row[k] * Wh0[k*DD + j];
        if (di < DIN) g_M[di*DD + j] = acc;
        else          g_b0[j] = acc + lb0[j];
    }
}

// ---------- prep: x0 = we[:,0,:] @ in_W + in_b ----------
__global__ void k_x0(const float* __restrict__ we, const float* __restrict__ in_W,
                     const float* __restrict__ in_b) {
    __shared__ float row[DIN];
    int b = blockIdx.x;
    for (int k = threadIdx.x; k < DIN; k += blockDim.x) row[k] = we[b*(LL*DIN) + k];
    __syncthreads();
    for (int j = threadIdx.x; j < DD; j += blockDim.x) {
        float acc = in_b[j];
        for (int k = 0; k < DIN; k++) acc += row[k] * in_W[k*DD + j];
        g_x0[b*DD + j] = acc;
    }
}

// ---------- U GEMM: U[t][b][:] = we[b,t,:] @ g_M + g_b0 ----------
__global__ __launch_bounds__(256) void k_ugemm(const float* __restrict__ we) {
    __shared__ float As[16*68];
    __shared__ float Bs[16*64];
    int bn = blockIdx.x;          // 0..4
    int bm = blockIdx.y;          // 0..2047
    int tid = threadIdx.x;
    int tr = tid >> 4, tc = tid & 15;
    int row0 = bm * 64, col0 = bn * 64;
    float acc[4][4] = {};
    for (int k0 = 0; k0 < DIN; k0 += 16) {
        for (int i = tid; i < 64*16; i += 256) {
            int kk = i & 15, m = i >> 4;
            int rr = row0 + m;
            int t = rr >> 9, b = rr & 511;
            As[kk*68 + m] = we[b*(LL*DIN) + t*DIN + k0 + kk];
        }
        for (int i = tid; i < 16*64; i += 256) {
            int n = i & 63, kk = i >> 6;
            int c = col0 + n;
            Bs[kk*64 + n] = (c < DD) ? g_M[(k0+kk)*DD + c] : 0.f;
        }
        __syncthreads();
        #pragma unroll
        for (int kk = 0; kk < 16; kk++) {
            float4 a = *(const float4*)&As[kk*68 + tr*4];
            float4 bv = *(const float4*)&Bs[kk*64 + tc*4];
            float av[4] = {a.x, a.y, a.z, a.w};
            float bvv[4] = {bv.x, bv.y, bv.z, bv.w};
            #pragma unroll
            for (int i = 0; i < 4; i++)
                #pragma unroll
                for (int j = 0; j < 4; j++) acc[i][j] += av[i] * bvv[j];
        }
        __syncthreads();
    }
    #pragma unroll
    for (int i = 0; i < 4; i++) {
        int rr = row0 + tr*4 + i;
        #pragma unroll
        for (int j = 0; j < 4; j++) {
            int c = col0 + tc*4 + j;
            if (c < DD) g_U[(size_t)rr*DD + c] = acc[i][j] + g_b0[c];
        }
    }
}

// ---------- persistent recurrence: all 256 steps, no inter-block deps ----------
// Block owns rows b0..b0+3. Thread j (j<300) owns column j of those rows.
// smem: double-buffered slot-sum [2][4][SUMSTR] + ring history [13][4][SUMSTR].
__global__ __launch_bounds__(320, 1) void k_rec(const float* __restrict__ Wr0,
                                                float* __restrict__ memo) {
    extern __shared__ float sm[];
    float* buf0 = sm;                         // 4*SUMSTR
    float* buf1 = sm + RROWS*SUMSTR;
    float* hist = sm + 2*RROWS*SUMSTR;        // [13][4][SUMSTR]
    const int j = threadIdx.x;
    const int b0 = blockIdx.x * RROWS;

    for (int i = j; i < RROWS*SUMSTR; i += 320) { buf0[i] = 0.f; buf1[i] = 0.f; }
    for (int i = j; i < NS*RROWS*SUMSTR; i += 320) hist[i] = 0.f;
    __syncthreads();

    int slot = 0;
    const float inv13 = 1.f / 13.f;
    for (int t = 0; t < LL; t++) {
        const float* __restrict__ sumIn = (t & 1) ? buf1 : buf0;
        float* __restrict__ sumOut      = (t & 1) ? buf0 : buf1;
        if (j < DD) {
            const float* __restrict__ Ut = g_U + (size_t)t*(BB*DD) + (size_t)b0*DD + j;
            float u0 = Ut[0], u1 = Ut[DD], u2 = Ut[2*DD], u3 = Ut[3*DD];
            float a0 = 0.f, a1 = 0.f, a2 = 0.f, a3 = 0.f;
            const float* __restrict__ wp = Wr0 + j;
            #pragma unroll 1
            for (int k = 0; k < DD; k += 4) {
                float w0 = wp[0], w1 = wp[DD], w2 = wp[2*DD], w3 = wp[3*DD];
                wp += 4*DD;
                float4 s0 = *(const float4*)&sumIn[0*SUMSTR + k];
                float4 s1 = *(const float4*)&sumIn[1*SUMSTR + k];
                float4 s2 = *(const float4*)&sumIn[2*SUMSTR + k];
                float4 s3 = *(const float4*)&sumIn[3*SUMSTR + k];
                a0 += s0.x*w0; a1 += s1.x*w0; a2 += s2.x*w0; a3 += s3.x*w0;
                a0 += s0.y*w1; a1 += s1.y*w1; a2 += s2.y*w1; a3 += s3.y*w1;
                a0 += s0.z*w2; a1 += s1.z*w2; a2 += s2.z*w2; a3 += s3.z*w2;
                a0 += s0.w*w3; a1 += s1.w*w3; a2 += s2.w*w3; a3 += s3.w*w3;
            }
            float h0 = tanhf(u0 + a0*inv13);
            float h1 = tanhf(u1 + a1*inv13);
            float h2 = tanhf(u2 + a2*inv13);
            float h3 = tanhf(u3 + a3*inv13);
            float* hs = hist + slot*(RROWS*SUMSTR);
            float o0 = hs[0*SUMSTR+j], o1 = hs[1*SUMSTR+j];
            float o2 = hs[2*SUMSTR+j], o3 = hs[3*SUMSTR+j];
            sumOut[0*SUMSTR+j] = sumIn[0*SUMSTR+j] + h0 - o0;
            sumOut[1*SUMSTR+j] = sumIn[1*SUMSTR+j] + h1 - o1;
            sumOut[2*SUMSTR+j] = sumIn[2*SUMSTR+j] + h2 - o2;
            sumOut[3*SUMSTR+j] = sumIn[3*SUMSTR+j] + h3 - o3;
            hs[0*SUMSTR+j] = h0; hs[1*SUMSTR+j] = h1;
            hs[2*SUMSTR+j] = h2; hs[3*SUMSTR+j] = h3;
        }
        slot++; if (slot == NS) slot = 0;
        __syncthreads();
    }

    // writeback final ring -> memo (layer 0 slices only)
    if (j < DD) {
        for (int s = 0; s < NS; s++) {
            const float* hs = hist + s*(RROWS*SUMSTR);
            #pragma unroll
            for (int r = 0; r < RROWS; r++)
                memo[(size_t)(b0+r)*(NS*NL*DD) + s*(NL*DD) + j] = hs[r*SUMSTR + j];
        }
    }
}

// ---------- epilogue gathers ----------
__global__ void k_gatherA(const float* __restrict__ memo) {
    int idx = blockIdx.x * blockDim.x + threadIdx.x;
    if (idx >= BB*KEP) return;
    int b = idx / KEP, k = idx % KEP;
    float v = 0.f;
    if (k < NS*DD)            { int s = k / DD, j = k % DD; v = memo[(size_t)b*(NS*NL*DD) + s*(NL*DD) + j]; }
    else if (k < NS*DD + DD)  { v = g_x0[b*DD + (k - NS*DD)]; }
    g_Aep[idx] = v;
}
__global__ void k_gatherW(const float* __restrict__ out_W, const float* __restrict__ skip_W) {
    int idx = blockIdx.x * blockDim.x + threadIdx.x;
    if (idx >= KEP*DIN) return;
    int k = idx / DIN, o = idx % DIN;
    float v = 0.f;
    if (k < NS*DD)            { int s = k / DD, j = k % DD; v = out_W[(s*(NL*DD) + j)*DIN + o]; }
    else if (k < NS*DD + DD)  { v = skip_W[(k - NS*DD)*DIN + o]; }
    g_Wep[idx] = v;
}

// ---------- epilogue GEMM: g_c = g_Aep @ g_Wep + (out_b + skip_b) ----------
__global__ __launch_bounds__(256) void k_epigemm(const float* __restrict__ out_b,
                                                 const float* __restrict__ skip_b) {
    __shared__ float As[16*68];
    __shared__ float Bs[16*64];
    int bn = blockIdx.x;   // 0..5
    int bm = blockIdx.y;   // 0..7
    int tid = threadIdx.x;
    int tr = tid >> 4, tc = tid & 15;
    int row0 = bm * 64, col0 = bn * 64;
    float acc[4][4] = {};
    for (int k0 = 0; k0 < KEP; k0 += 16) {
        for (int i = tid; i < 64*16; i += 256) {
            int kk = i & 15, m = i >> 4;
            As[kk*68 + m] = g_Aep[(row0+m)*KEP + k0 + kk];
        }
        for (int i = tid; i < 16*64; i += 256) {
            int n = i & 63, kk = i >> 6;
            Bs[kk*64 + n] = g_Wep[(k0+kk)*DIN + col0 + n];
        }
        __syncthreads();
        #pragma unroll
        for (int kk = 0; kk < 16; kk++) {
            float4 a = *(const float4*)&As[kk*68 + tr*4];
            float4 bv = *(const float4*)&Bs[kk*64 + tc*4];
            float av[4] = {a.x, a.y, a.z, a.w};
            float bvv[4] = {bv.x, bv.y, bv.z, bv.w};
            #pragma unroll
            for (int i = 0; i < 4; i++)
                #pragma unroll
                for (int j = 0; j < 4; j++) acc[i][j] += av[i] * bvv[j];
        }
        __syncthreads();
    }
    #pragma unroll
    for (int i = 0; i < 4; i++) {
        int rr = row0 + tr*4 + i;
        #pragma unroll
        for (int j = 0; j < 4; j++) {
            int c = col0 + tc*4 + j;
            g_c[rr*DIN + c] = acc[i][j] + out_b[c] + skip_b[c];
        }
    }
}

// ---------- LayerNorm ----------
__device__ __forceinline__ float blk_reduce(float v, float* sm) {
    int lane = threadIdx.x & 31, w = threadIdx.x >> 5;
    #pragma unroll
    for (int o = 16; o > 0; o >>= 1) v += __shfl_xor_sync(0xffffffff, v, o);
    if (lane == 0) sm[w] = v;
    __syncthreads();
    v = (threadIdx.x < 4) ? sm[threadIdx.x] : 0.f;
    if (threadIdx.x < 4) {
        #pragma unroll
        for (int o = 2; o > 0; o >>= 1) v += __shfl_xor_sync(0xf, v, o);
        if (threadIdx.x == 0) sm[0] = v;
    }
    __syncthreads();
    return sm[0];
}
__global__ __launch_bounds__(128) void k_ln(const float* __restrict__ g,
                                            const float* __restrict__ be,
                                            float* __restrict__ out) {
    __shared__ float sm[4];
    int b = blockIdx.x, tid = threadIdx.x;
    float v[3];
    float s = 0.f;
    #pragma unroll
    for (int r = 0; r < 3; r++) { v[r] = g_c[b*DIN + tid + r*128]; s += v[r]; }
    float mu = blk_reduce(s, sm) * (1.f / DIN);
    __syncthreads();
    float q = 0.f;
    #pragma unroll
    for (int r = 0; r < 3; r++) { float d = v[r] - mu; q += d * d; }
    float var = blk_reduce(q, sm) * (1.f / DIN);
    float rs = rsqrtf(var + EPSL);
    #pragma unroll
    for (int r = 0; r < 3; r++) {
        int i = tid + r*128;
        out[C_OFF + b*DIN + i] = (v[r] - mu) * rs * g[i] + be[i];
    }
}

// ---------- scoring head ----------
__global__ __launch_bounds__(64) void k_logit(const float* __restrict__ W1,
                                              const float* __restrict__ b1,
                                              const float* __restrict__ W2,
                                              const float* __restrict__ b2,
                                              float* __restrict__ out) {
    __shared__ float cs[DIN];
    __shared__ float red[2];
    int b = blockIdx.x, tid = threadIdx.x;
    for (int i = tid; i < DIN; i += 64) cs[i] = out[C_OFF + b*DIN + i];
    __syncthreads();
    float acc = b1[tid];
    for (int i = 0; i < DIN; i++) acc += cs[i] * W1[i*64 + tid];
    float r = fmaxf(acc, 0.f) * W2[tid];
    #pragma unroll
    for (int o = 16; o > 0; o >>= 1) r += __shfl_xor_sync(0xffffffff, r, o);
    if ((tid & 31) == 0) red[tid >> 5] = r;
    __syncthreads();
    if (tid == 0) out[LOGIT_OFF + b] = red[0] + red[1] + b2[0];
}

// ---------- launcher ----------
extern "C" void kernel_launch(void* const* d_in, const int* in_sizes, int n_in,
                              void* d_out, int out_size) {
    const float* we     = (const float*)d_in[0];
    const float* in_W   = (const float*)d_in[1];
    const float* in_b   = (const float*)d_in[2];
    const float* Wh     = (const float*)d_in[3];   // Wh0 = first 300*300
    const float* Wr     = (const float*)d_in[4];   // Wr0 = first 300*300
    const float* lb     = (const float*)d_in[5];   // lb0 = first 300
    const float* skip_W = (const float*)d_in[6];
    const float* skip_b = (const float*)d_in[7];
    const float* out_W  = (const float*)d_in[8];
    const float* out_b  = (const float*)d_in[9];
    const float* ln_g   = (const float*)d_in[10];
    const float* ln_b   = (const float*)d_in[11];
    const float* sh_W1  = (const float*)d_in[12];
    const float* sh_b1  = (const float*)d_in[13];
    const float* sh_W2  = (const float*)d_in[14];
    const float* sh_b2  = (const float*)d_in[15];
    float* out = (float*)d_out;
    float* memo = out + MEM_OFF;

    // recurrence kernel needs >48KB dynamic smem
    const int rec_smem = (2*RROWS + NS*RROWS) * SUMSTR * (int)sizeof(float); // 72960
    cudaFuncSetAttribute(k_rec, cudaFuncAttributeMaxDynamicSharedMemorySize, rec_smem);

    // init output mem region (layers 1..7 stay zero)
    k_zero_out<<<(MEM_SIZE + 255) / 256, 256>>>(memo, MEM_SIZE);

    // prep
    k_prep_M<<<DIN + 1, 128>>>(in_W, in_b, Wh, lb);
    k_x0<<<BB, 128>>>(we, in_W, in_b);

    // parallel input projection: U[t][b][:] for all t
    k_ugemm<<<dim3(5, 2048), 256>>>(we);

    // persistent recurrence: one launch, all 256 steps (batch-parallel)
    k_rec<<<BB / RROWS, 320, rec_smem>>>(Wr, memo);

    // epilogue
    k_gatherA<<<(BB*KEP + 255) / 256, 256>>>(memo);
    k_gatherW<<<(KEP*DIN + 255) / 256, 256>>>(out_W, skip_W);
    k_epigemm<<<dim3(6, 8), 256>>>(out_b, skip_b);
    k_ln<<<BB, 128>>>(ln_g, ln_b, out);
    k_logit<<<BB, 64>>>(sh_W1, sh_b1, sh_W2, sh_b2, out);
}

// round 4
// speedup vs baseline: 3.4743x; 1.6734x over previous
#include <cuda_runtime.h>
#include <math.h>

#define BB   512
#define LL   256
#define DIN  384
#define DD   300
#define NS   13
#define NL   8
#define EPSL 1e-5f

#define KEP  4224                       // 13*300 + 300 = 4200, padded
#define C_OFF 0
#define MEM_OFF   (BB*DIN)              // 196608
#define MEM_SIZE  (BB*NS*NL*DD)         // 15974400
#define LOGIT_OFF (MEM_OFF + MEM_SIZE)  // 16171008

// ---------- f32x2 packed helpers ----------
__device__ __forceinline__ unsigned long long pk2(float lo, float hi) {
    unsigned long long d;
    asm("mov.b64 %0, {%1, %2};" : "=l"(d)
        : "r"(__float_as_uint(lo)), "r"(__float_as_uint(hi)));
    return d;
}
__device__ __forceinline__ void upk2(unsigned long long v, float& lo, float& hi) {
    unsigned int a, b;
    asm("mov.b64 {%0, %1}, %2;" : "=r"(a), "=r"(b) : "l"(v));
    lo = __uint_as_float(a); hi = __uint_as_float(b);
}
__device__ __forceinline__ unsigned long long fma2(unsigned long long a,
                                                   unsigned long long b,
                                                   unsigned long long c) {
    unsigned long long d;
    asm("fma.rn.f32x2 %0, %1, %2, %3;" : "=l"(d) : "l"(a), "l"(b), "l"(c));
    return d;
}
__device__ __forceinline__ unsigned long long add2(unsigned long long a,
                                                   unsigned long long b) {
    unsigned long long d;
    asm("add.rn.f32x2 %0, %1, %2;" : "=l"(d) : "l"(a), "l"(b));
    return d;
}

// ---------- device scratch ----------
__device__ float g_M[DIN*DD];           // fused in_W @ Wh0
__device__ float g_b0[DD];              // in_b @ Wh0 + lb0
__device__ float g_U[(size_t)LL*BB*DD]; // U[t][b][j]
__device__ float g_x0[BB*DD];
__device__ float g_Aep[BB*KEP];
__device__ float g_Wep[KEP*DIN];
__device__ float g_c[BB*DIN];           // pre-LN c

// ---------- misc ----------
__global__ void k_zero_out(float* p, int n) {
    int i = blockIdx.x * blockDim.x + threadIdx.x;
    if (i < n) p[i] = 0.f;
}

// ---------- prep: g_M = in_W @ Wh0 ; g_b0 = in_b @ Wh0 + lb0 ----------
__global__ void k_prep_M(const float* __restrict__ in_W, const float* __restrict__ in_b,
                         const float* __restrict__ Wh0, const float* __restrict__ lb0) {
    __shared__ float row[DD];
    int di = blockIdx.x;
    const float* src = (di < DIN) ? (in_W + di*DD) : in_b;
    for (int k = threadIdx.x; k < DD; k += blockDim.x) row[k] = src[k];
    __syncthreads();
    for (int j = threadIdx.x; j < DD; j += blockDim.x) {
        float acc = 0.f;
        for (int k = 0; k < DD; k++) acc += row[k] * Wh0[k*DD + j];
        if (di < DIN) g_M[di*DD + j] = acc;
        else          g_b0[j] = acc + lb0[j];
    }
}

// ---------- prep: x0 = we[:,0,:] @ in_W + in_b ----------
__global__ void k_x0(const float* __restrict__ we, const float* __restrict__ in_W,
                     const float* __restrict__ in_b) {
    __shared__ float row[DIN];
    int b = blockIdx.x;
    for (int k = threadIdx.x; k < DIN; k += blockDim.x) row[k] = we[b*(LL*DIN) + k];
    __syncthreads();
    for (int j = threadIdx.x; j < DD; j += blockDim.x) {
        float acc = in_b[j];
        for (int k = 0; k < DIN; k++) acc += row[k] * in_W[k*DD + j];
        g_x0[b*DD + j] = acc;
    }
}

// ---------- U GEMM (f32x2): 128x64 tile, 8x4 micro ----------
__global__ __launch_bounds__(256) void k_ugemm(const float* __restrict__ we) {
    __shared__ float As[16*132];          // [kk][m], stride 132
    __shared__ float2 Bs2[16*64];         // duplicated b values
    int bn = blockIdx.x;                  // 0..4  (N pad 320)
    int bm = blockIdx.y;                  // 0..1023
    int tid = threadIdx.x;
    int tr = tid >> 4, tc = tid & 15;
    int row0 = bm * 128, col0 = bn * 64;
    unsigned long long acc[4][4];
    #pragma unroll
    for (int i = 0; i < 4; i++)
        #pragma unroll
        for (int j = 0; j < 4; j++) acc[i][j] = 0ull;
    for (int k0 = 0; k0 < DIN; k0 += 16) {
        for (int i = tid; i < 128*16; i += 256) {
            int kk = i & 15, m = i >> 4;
            int rr = row0 + m;
            int t = rr >> 9, b = rr & 511;
            As[kk*132 + m] = we[(size_t)b*(LL*DIN) + t*DIN + k0 + kk];
        }
        for (int i = tid; i < 16*64; i += 256) {
            int n = i & 63, kk = i >> 6;
            int c = col0 + n;
            float v = (c < DD) ? g_M[(k0+kk)*DD + c] : 0.f;
            Bs2[kk*64 + n] = make_float2(v, v);
        }
        __syncthreads();
        #pragma unroll
        for (int kk = 0; kk < 16; kk++) {
            ulonglong2 aA = *(const ulonglong2*)&As[kk*132 + tr*8];
            ulonglong2 aB = *(const ulonglong2*)&As[kk*132 + tr*8 + 4];
            ulonglong2 bA = *(const ulonglong2*)&Bs2[kk*64 + tc*4];
            ulonglong2 bB = *(const ulonglong2*)&Bs2[kk*64 + tc*4 + 2];
            unsigned long long av[4] = {aA.x, aA.y, aB.x, aB.y};
            unsigned long long bv[4] = {bA.x, bA.y, bB.x, bB.y};
            #pragma unroll
            for (int i = 0; i < 4; i++)
                #pragma unroll
                for (int j = 0; j < 4; j++) acc[i][j] = fma2(av[i], bv[j], acc[i][j]);
        }
        __syncthreads();
    }
    #pragma unroll
    for (int i = 0; i < 4; i++) {
        int r0 = row0 + tr*8 + 2*i;
        #pragma unroll
        for (int j = 0; j < 4; j++) {
            int c = col0 + tc*4 + j;
            if (c < DD) {
                float v0, v1; upk2(acc[i][j], v0, v1);
                float bb = g_b0[c];
                g_U[(size_t)r0*DD + c]     = v0 + bb;
                g_U[(size_t)(r0+1)*DD + c] = v1 + bb;
            }
        }
    }
}

// ---------- persistent recurrence ----------
// 640 threads = 4 k-quarters x 160 slots (150 active col-pairs each).
// Thread (q, p) handles cols (2p, 2p+1), rows b0..b0+3, k in [q*76, q*76+76).
// Wr0 rows: first 40 per quarter stashed in smem (194.5 KB); rest streamed.
// sum & ring history: sum as float4-per-column (rows packed); ring lives in memo.
#define RQK   76
#define RSTK  40
#define RSLOT 160
__global__ __launch_bounds__(640, 1) void k_rec(const float* __restrict__ Wr0,
                                                float* __restrict__ memo) {
    extern __shared__ char sm_raw[];
    float4* sumA = (float4*)sm_raw;                               // 304
    float4* sumB = sumA + 304;                                    // 304
    unsigned long long* part = (unsigned long long*)(sumB + 304); // 3*160*4
    float2* wst = (float2*)(part + 3*RSLOT*4);                    // [4][40][152]

    const int tid = threadIdx.x;
    const int quarter = tid / RSLOT;
    const int p = tid - quarter * RSLOT;
    const int b0 = blockIdx.x * 4;
    const bool act = (p < 150);

    // stash Wr0 rows (40 per quarter) as float2 pairs
    for (int idx = tid; idx < 4*RSTK*150; idx += 640) {
        int q2 = idx / (RSTK*150);
        int rem = idx - q2*(RSTK*150);
        int kk = rem / 150, pp = rem - kk*150;
        int krow = q2*RQK + kk;
        wst[(q2*RSTK + kk)*152 + pp] = *((const float2*)(Wr0 + (size_t)krow*DD) + pp);
    }
    for (int idx = tid; idx < 304; idx += 640) {
        sumA[idx] = make_float4(0.f, 0.f, 0.f, 0.f);
        sumB[idx] = make_float4(0.f, 0.f, 0.f, 0.f);
    }
    __syncthreads();

    const float inv13 = 1.f / 13.f;
    int slot = 0;
    for (int t = 0; t < LL; t++) {
        const float4* __restrict__ sumIn = (t & 1) ? sumB : sumA;
        float4* __restrict__ sumOut      = (t & 1) ? sumA : sumB;
        const int c0 = 2*p, c1 = 2*p + 1;

        float u[8], oldv[8];
        if (quarter == 0 && act) {            // prefetch U + old ring values
            #pragma unroll
            for (int r = 0; r < 4; r++) {
                size_t ub = (size_t)t*(BB*DD) + (size_t)(b0+r)*DD;
                u[r]   = g_U[ub + c0];
                u[4+r] = g_U[ub + c1];
                size_t mb = (size_t)(b0+r)*(NS*NL*DD) + (size_t)slot*(NL*DD);
                oldv[r]   = memo[mb + c0];
                oldv[4+r] = memo[mb + c1];
            }
        }

        unsigned long long a0 = 0ull, a1 = 0ull, a2 = 0ull, a3 = 0ull;
        if (act) {
            const int kb = quarter * RQK;
            const ulonglong2* __restrict__ sp = (const ulonglong2*)(sumIn + kb);
            const float2* __restrict__ wsq = wst + (quarter*RSTK)*152 + p;
            #pragma unroll 4
            for (int kk = 0; kk < RSTK; kk++) {
                float2 w = wsq[kk*152];
                ulonglong2 s = sp[kk];
                unsigned long long wa = pk2(w.x, w.x), wb = pk2(w.y, w.y);
                a0 = fma2(s.x, wa, a0); a1 = fma2(s.y, wa, a1);
                a2 = fma2(s.x, wb, a2); a3 = fma2(s.y, wb, a3);
            }
            #pragma unroll 4
            for (int kk = RSTK; kk < RQK; kk++) {
                float2 w = *((const float2*)(Wr0 + (size_t)(kb+kk)*DD) + p);
                ulonglong2 s = sp[kk];
                unsigned long long wa = pk2(w.x, w.x), wb = pk2(w.y, w.y);
                a0 = fma2(s.x, wa, a0); a1 = fma2(s.y, wa, a1);
                a2 = fma2(s.x, wb, a2); a3 = fma2(s.y, wb, a3);
            }
        }
        if (quarter != 0 && act) {
            unsigned long long* pp_ = part + ((quarter-1)*RSLOT + p)*4;
            pp_[0] = a0; pp_[1] = a1; pp_[2] = a2; pp_[3] = a3;
        }
        __syncthreads();
        if (quarter == 0 && act) {
            #pragma unroll
            for (int qq = 0; qq < 3; qq++) {
                const unsigned long long* pp_ = part + (qq*RSLOT + p)*4;
                a0 = add2(a0, pp_[0]); a1 = add2(a1, pp_[1]);
                a2 = add2(a2, pp_[2]); a3 = add2(a3, pp_[3]);
            }
            float v[8];
            upk2(a0, v[0], v[1]); upk2(a1, v[2], v[3]);   // col0 rows 0..3
            upk2(a2, v[4], v[5]); upk2(a3, v[6], v[7]);   // col1 rows 0..3
            float h[8];
            #pragma unroll
            for (int i = 0; i < 8; i++) h[i] = tanhf(u[i] + v[i]*inv13);
            float4 si0 = sumIn[c0], si1 = sumIn[c1];
            sumOut[c0] = make_float4(si0.x + h[0]-oldv[0], si0.y + h[1]-oldv[1],
                                     si0.z + h[2]-oldv[2], si0.w + h[3]-oldv[3]);
            sumOut[c1] = make_float4(si1.x + h[4]-oldv[4], si1.y + h[5]-oldv[5],
                                     si1.z + h[6]-oldv[6], si1.w + h[7]-oldv[7]);
            #pragma unroll
            for (int r = 0; r < 4; r++) {
                size_t mb = (size_t)(b0+r)*(NS*NL*DD) + (size_t)slot*(NL*DD);
                memo[mb + c0] = h[r];
                memo[mb + c1] = h[4+r];
            }
        }
        slot++; if (slot == NS) slot = 0;
        __syncthreads();
    }
}

// ---------- epilogue gathers ----------
__global__ void k_gatherA(const float* __restrict__ memo) {
    int idx = blockIdx.x * blockDim.x + threadIdx.x;
    if (idx >= BB*KEP) return;
    int b = idx / KEP, k = idx % KEP;
    float v = 0.f;
    if (k < NS*DD)            { int s = k / DD, j = k % DD; v = memo[(size_t)b*(NS*NL*DD) + s*(NL*DD) + j]; }
    else if (k < NS*DD + DD)  { v = g_x0[b*DD + (k - NS*DD)]; }
    g_Aep[idx] = v;
}
__global__ void k_gatherW(const float* __restrict__ out_W, const float* __restrict__ skip_W) {
    int idx = blockIdx.x * blockDim.x + threadIdx.x;
    if (idx >= KEP*DIN) return;
    int k = idx / DIN, o = idx % DIN;
    float v = 0.f;
    if (k < NS*DD)            { int s = k / DD, j = k % DD; v = out_W[(s*(NL*DD) + j)*DIN + o]; }
    else if (k < NS*DD + DD)  { v = skip_W[(k - NS*DD)*DIN + o]; }
    g_Wep[idx] = v;
}

// ---------- epilogue GEMM (f32x2): 128x64 tile, 8x4 micro ----------
__global__ __launch_bounds__(256) void k_epigemm(const float* __restrict__ out_b,
                                                 const float* __restrict__ skip_b) {
    __shared__ float As[16*132];
    __shared__ float2 Bs2[16*64];
    int bn = blockIdx.x;   // 0..5
    int bm = blockIdx.y;   // 0..3
    int tid = threadIdx.x;
    int tr = tid >> 4, tc = tid & 15;
    int row0 = bm * 128, col0 = bn * 64;
    unsigned long long acc[4][4];
    #pragma unroll
    for (int i = 0; i < 4; i++)
        #pragma unroll
        for (int j = 0; j < 4; j++) acc[i][j] = 0ull;
    for (int k0 = 0; k0 < KEP; k0 += 16) {
        for (int i = tid; i < 128*16; i += 256) {
            int kk = i & 15, m = i >> 4;
            As[kk*132 + m] = g_Aep[(size_t)(row0+m)*KEP + k0 + kk];
        }
        for (int i = tid; i < 16*64; i += 256) {
            int n = i & 63, kk = i >> 6;
            float v = g_Wep[(k0+kk)*DIN + col0 + n];
            Bs2[kk*64 + n] = make_float2(v, v);
        }
        __syncthreads();
        #pragma unroll
        for (int kk = 0; kk < 16; kk++) {
            ulonglong2 aA = *(const ulonglong2*)&As[kk*132 + tr*8];
            ulonglong2 aB = *(const ulonglong2*)&As[kk*132 + tr*8 + 4];
            ulonglong2 bA = *(const ulonglong2*)&Bs2[kk*64 + tc*4];
            ulonglong2 bB = *(const ulonglong2*)&Bs2[kk*64 + tc*4 + 2];
            unsigned long long av[4] = {aA.x, aA.y, aB.x, aB.y};
            unsigned long long bv[4] = {bA.x, bA.y, bB.x, bB.y};
            #pragma unroll
            for (int i = 0; i < 4; i++)
                #pragma unroll
                for (int j = 0; j < 4; j++) acc[i][j] = fma2(av[i], bv[j], acc[i][j]);
        }
        __syncthreads();
    }
    #pragma unroll
    for (int i = 0; i < 4; i++) {
        int r0 = row0 + tr*8 + 2*i;
        #pragma unroll
        for (int j = 0; j < 4; j++) {
            int c = col0 + tc*4 + j;
            float v0, v1; upk2(acc[i][j], v0, v1);
            float bb = out_b[c] + skip_b[c];
            g_c[r0*DIN + c]     = v0 + bb;
            g_c[(r0+1)*DIN + c] = v1 + bb;
        }
    }
}

// ---------- LayerNorm ----------
__device__ __forceinline__ float blk_reduce(float v, float* sm) {
    int lane = threadIdx.x & 31, w = threadIdx.x >> 5;
    #pragma unroll
    for (int o = 16; o > 0; o >>= 1) v += __shfl_xor_sync(0xffffffff, v, o);
    if (lane == 0) sm[w] = v;
    __syncthreads();
    v = (threadIdx.x < 4) ? sm[threadIdx.x] : 0.f;
    if (threadIdx.x < 4) {
        #pragma unroll
        for (int o = 2; o > 0; o >>= 1) v += __shfl_xor_sync(0xf, v, o);
        if (threadIdx.x == 0) sm[0] = v;
    }
    __syncthreads();
    return sm[0];
}
__global__ __launch_bounds__(128) void k_ln(const float* __restrict__ g,
                                            const float* __restrict__ be,
                                            float* __restrict__ out) {
    __shared__ float sm[4];
    int b = blockIdx.x, tid = threadIdx.x;
    float v[3];
    float s = 0.f;
    #pragma unroll
    for (int r = 0; r < 3; r++) { v[r] = g_c[b*DIN + tid + r*128]; s += v[r]; }
    float mu = blk_reduce(s, sm) * (1.f / DIN);
    __syncthreads();
    float q = 0.f;
    #pragma unroll
    for (int r = 0; r < 3; r++) { float d = v[r] - mu; q += d * d; }
    float var = blk_reduce(q, sm) * (1.f / DIN);
    float rs = rsqrtf(var + EPSL);
    #pragma unroll
    for (int r = 0; r < 3; r++) {
        int i = tid + r*128;
        out[C_OFF + b*DIN + i] = (v[r] - mu) * rs * g[i] + be[i];
    }
}

// ---------- scoring head ----------
__global__ __launch_bounds__(64) void k_logit(const float* __restrict__ W1,
                                              const float* __restrict__ b1,
                                              const float* __restrict__ W2,
                                              const float* __restrict__ b2,
                                              float* __restrict__ out) {
    __shared__ float cs[DIN];
    __shared__ float red[2];
    int b = blockIdx.x, tid = threadIdx.x;
    for (int i = tid; i < DIN; i += 64) cs[i] = out[C_OFF + b*DIN + i];
    __syncthreads();
    float acc = b1[tid];
    for (int i = 0; i < DIN; i++) acc += cs[i] * W1[i*64 + tid];
    float r = fmaxf(acc, 0.f) * W2[tid];
    #pragma unroll
    for (int o = 16; o > 0; o >>= 1) r += __shfl_xor_sync(0xffffffff, r, o);
    if ((tid & 31) == 0) red[tid >> 5] = r;
    __syncthreads();
    if (tid == 0) out[LOGIT_OFF + b] = red[0] + red[1] + b2[0];
}

// ---------- launcher ----------
extern "C" void kernel_launch(void* const* d_in, const int* in_sizes, int n_in,
                              void* d_out, int out_size) {
    const float* we     = (const float*)d_in[0];
    const float* in_W   = (const float*)d_in[1];
    const float* in_b   = (const float*)d_in[2];
    const float* Wh     = (const float*)d_in[3];
    const float* Wr     = (const float*)d_in[4];
    const float* lb     = (const float*)d_in[5];
    const float* skip_W = (const float*)d_in[6];
    const float* skip_b = (const float*)d_in[7];
    const float* out_W  = (const float*)d_in[8];
    const float* out_b  = (const float*)d_in[9];
    const float* ln_g   = (const float*)d_in[10];
    const float* ln_b   = (const float*)d_in[11];
    const float* sh_W1  = (const float*)d_in[12];
    const float* sh_b1  = (const float*)d_in[13];
    const float* sh_W2  = (const float*)d_in[14];
    const float* sh_b2  = (const float*)d_in[15];
    float* out = (float*)d_out;
    float* memo = out + MEM_OFF;

    // smem: sum(2*304*16) + partial(3*160*4*8) + stash(4*40*152*8) = 219648 B
    const int rec_smem = 304*16*2 + 3*RSLOT*4*8 + 4*RSTK*152*8;
    cudaFuncSetAttribute(k_rec, cudaFuncAttributeMaxDynamicSharedMemorySize, rec_smem);

    // init output mem region (layers 1..7 stay zero; also ring "old" reads)
    k_zero_out<<<(MEM_SIZE + 255) / 256, 256>>>(memo, MEM_SIZE);

    // prep
    k_prep_M<<<DIN + 1, 128>>>(in_W, in_b, Wh, lb);
    k_x0<<<BB, 128>>>(we, in_W, in_b);

    // parallel input projection
    k_ugemm<<<dim3(5, 1024), 256>>>(we);

    // persistent recurrence
    k_rec<<<BB / 4, 640, rec_smem>>>(Wr, memo);

    // epilogue
    k_gatherA<<<(BB*KEP + 255) / 256, 256>>>(memo);
    k_gatherW<<<(KEP*DIN + 255) / 256, 256>>>(out_W, skip_W);
    k_epigemm<<<dim3(6, 4), 256>>>(out_b, skip_b);
    k_ln<<<BB, 128>>>(ln_g, ln_b, out);
    k_logit<<<BB, 64>>>(sh_W1, sh_b1, sh_W2, sh_b2, out);
}

// round 5
// speedup vs baseline: 3.4834x; 1.0026x over previous
#include <cuda_runtime.h>
#include <math.h>

#define BB   512
#define LL   256
#define DIN  384
#define DD   300
#define NS   13
#define NL   8
#define EPSL 1e-5f

#define KEP  4224                       // 13*300 + 300 = 4200, padded
#define C_OFF 0
#define MEM_OFF   (BB*DIN)              // 196608
#define MEM_SIZE  (BB*NS*NL*DD)         // 15974400
#define LOGIT_OFF (MEM_OFF + MEM_SIZE)  // 16171008

// ---------- f32x2 packed helpers ----------
__device__ __forceinline__ unsigned long long pk2(float lo, float hi) {
    unsigned long long d;
    asm("mov.b64 %0, {%1, %2};" : "=l"(d)
        : "r"(__float_as_uint(lo)), "r"(__float_as_uint(hi)));
    return d;
}
__device__ __forceinline__ void upk2(unsigned long long v, float& lo, float& hi) {
    unsigned int a, b;
    asm("mov.b64 {%0, %1}, %2;" : "=r"(a), "=r"(b) : "l"(v));
    lo = __uint_as_float(a); hi = __uint_as_float(b);
}
__device__ __forceinline__ unsigned long long fma2(unsigned long long a,
                                                   unsigned long long b,
                                                   unsigned long long c) {
    unsigned long long d;
    asm("fma.rn.f32x2 %0, %1, %2, %3;" : "=l"(d) : "l"(a), "l"(b), "l"(c));
    return d;
}
__device__ __forceinline__ unsigned long long add2(unsigned long long a,
                                                   unsigned long long b) {
    unsigned long long d;
    asm("add.rn.f32x2 %0, %1, %2;" : "=l"(d) : "l"(a), "l"(b));
    return d;
}

// ---------- device scratch ----------
__device__ float g_M[DIN*DD];           // fused in_W @ Wh0
__device__ float g_b0[DD];              // in_b @ Wh0 + lb0
__device__ float g_U[(size_t)LL*BB*DD]; // U[t][b][j]
__device__ float g_x0[BB*DD];
__device__ float g_Aep[BB*KEP];
__device__ float g_Wep[KEP*DIN];
__device__ float g_c[BB*DIN];           // pre-LN c

// ---------- misc ----------
__global__ void k_zero_out(float* p, int n) {
    int i = blockIdx.x * blockDim.x + threadIdx.x;
    if (i < n) p[i] = 0.f;
}

// ---------- prep: g_M = in_W @ Wh0 ; g_b0 = in_b @ Wh0 + lb0 ----------
__global__ void k_prep_M(const float* __restrict__ in_W, const float* __restrict__ in_b,
                         const float* __restrict__ Wh0, const float* __restrict__ lb0) {
    __shared__ float row[DD];
    int di = blockIdx.x;
    const float* src = (di < DIN) ? (in_W + di*DD) : in_b;
    for (int k = threadIdx.x; k < DD; k += blockDim.x) row[k] = src[k];
    __syncthreads();
    for (int j = threadIdx.x; j < DD; j += blockDim.x) {
        float acc = 0.f;
        for (int k = 0; k < DD; k++) acc += row[k] * Wh0[k*DD + j];
        if (di < DIN) g_M[di*DD + j] = acc;
        else          g_b0[j] = acc + lb0[j];
    }
}

// ---------- prep: x0 = we[:,0,:] @ in_W + in_b ----------
__global__ void k_x0(const float* __restrict__ we, const float* __restrict__ in_W,
                     const float* __restrict__ in_b) {
    __shared__ float row[DIN];
    int b = blockIdx.x;
    for (int k = threadIdx.x; k < DIN; k += blockDim.x) row[k] = we[b*(LL*DIN) + k];
    __syncthreads();
    for (int j = threadIdx.x; j < DD; j += blockDim.x) {
        float acc = in_b[j];
        for (int k = 0; k < DIN; k++) acc += row[k] * in_W[k*DD + j];
        g_x0[b*DD + j] = acc;
    }
}

// ---------- U GEMM (f32x2): 128x64 tile, 8x4 micro ----------
__global__ __launch_bounds__(256) void k_ugemm(const float* __restrict__ we) {
    __shared__ float As[16*132];          // [kk][m], stride 132
    __shared__ float2 Bs2[16*64];         // duplicated b values
    int bn = blockIdx.x;                  // 0..4  (N pad 320)
    int bm = blockIdx.y;                  // 0..1023
    int tid = threadIdx.x;
    int tr = tid >> 4, tc = tid & 15;
    int row0 = bm * 128, col0 = bn * 64;
    unsigned long long acc[4][4];
    #pragma unroll
    for (int i = 0; i < 4; i++)
        #pragma unroll
        for (int j = 0; j < 4; j++) acc[i][j] = 0ull;
    for (int k0 = 0; k0 < DIN; k0 += 16) {
        for (int i = tid; i < 128*16; i += 256) {
            int kk = i & 15, m = i >> 4;
            int rr = row0 + m;
            int t = rr >> 9, b = rr & 511;
            As[kk*132 + m] = we[(size_t)b*(LL*DIN) + t*DIN + k0 + kk];
        }
        for (int i = tid; i < 16*64; i += 256) {
            int n = i & 63, kk = i >> 6;
            int c = col0 + n;
            float v = (c < DD) ? g_M[(k0+kk)*DD + c] : 0.f;
            Bs2[kk*64 + n] = make_float2(v, v);
        }
        __syncthreads();
        #pragma unroll
        for (int kk = 0; kk < 16; kk++) {
            ulonglong2 aA = *(const ulonglong2*)&As[kk*132 + tr*8];
            ulonglong2 aB = *(const ulonglong2*)&As[kk*132 + tr*8 + 4];
            ulonglong2 bA = *(const ulonglong2*)&Bs2[kk*64 + tc*4];
            ulonglong2 bB = *(const ulonglong2*)&Bs2[kk*64 + tc*4 + 2];
            unsigned long long av[4] = {aA.x, aA.y, aB.x, aB.y};
            unsigned long long bv[4] = {bA.x, bA.y, bB.x, bB.y};
            #pragma unroll
            for (int i = 0; i < 4; i++)
                #pragma unroll
                for (int j = 0; j < 4; j++) acc[i][j] = fma2(av[i], bv[j], acc[i][j]);
        }
        __syncthreads();
    }
    #pragma unroll
    for (int i = 0; i < 4; i++) {
        int r0 = row0 + tr*8 + 2*i;
        #pragma unroll
        for (int j = 0; j < 4; j++) {
            int c = col0 + tc*4 + j;
            if (c < DD) {
                float v0, v1; upk2(acc[i][j], v0, v1);
                float bb = g_b0[c];
                g_U[(size_t)r0*DD + c]     = v0 + bb;
                g_U[(size_t)(r0+1)*DD + c] = v1 + bb;
            }
        }
    }
}

// ---------- persistent recurrence ----------
// 640 threads = 4 k-quarters x 160 slots (150 active col-pairs each).
// Thread (q, p) handles cols (2p, 2p+1), rows b0..b0+3, k in [q*76, q*76+76).
// Wr0 rows: first 40 per quarter stashed in smem (194.5 KB); rest streamed.
// sum & ring history: sum as float4-per-column (rows packed); ring lives in memo.
#define RQK   76
#define RSTK  40
#define RSLOT 160
__global__ __launch_bounds__(640, 1) void k_rec(const float* __restrict__ Wr0,
                                                float* __restrict__ memo) {
    extern __shared__ char sm_raw[];
    float4* sumA = (float4*)sm_raw;                               // 304
    float4* sumB = sumA + 304;                                    // 304
    unsigned long long* part = (unsigned long long*)(sumB + 304); // 3*160*4
    float2* wst = (float2*)(part + 3*RSLOT*4);                    // [4][40][152]

    const int tid = threadIdx.x;
    const int quarter = tid / RSLOT;
    const int p = tid - quarter * RSLOT;
    const int b0 = blockIdx.x * 4;
    const bool act = (p < 150);

    // stash Wr0 rows (40 per quarter) as float2 pairs
    for (int idx = tid; idx < 4*RSTK*150; idx += 640) {
        int q2 = idx / (RSTK*150);
        int rem = idx - q2*(RSTK*150);
        int kk = rem / 150, pp = rem - kk*150;
        int krow = q2*RQK + kk;
        wst[(q2*RSTK + kk)*152 + pp] = *((const float2*)(Wr0 + (size_t)krow*DD) + pp);
    }
    for (int idx = tid; idx < 304; idx += 640) {
        sumA[idx] = make_float4(0.f, 0.f, 0.f, 0.f);
        sumB[idx] = make_float4(0.f, 0.f, 0.f, 0.f);
    }
    __syncthreads();

    const float inv13 = 1.f / 13.f;
    int slot = 0;
    for (int t = 0; t < LL; t++) {
        const float4* __restrict__ sumIn = (t & 1) ? sumB : sumA;
        float4* __restrict__ sumOut      = (t & 1) ? sumA : sumB;
        const int c0 = 2*p, c1 = 2*p + 1;

        float u[8], oldv[8];
        if (quarter == 0 && act) {            // prefetch U + old ring values
            #pragma unroll
            for (int r = 0; r < 4; r++) {
                size_t ub = (size_t)t*(BB*DD) + (size_t)(b0+r)*DD;
                u[r]   = g_U[ub + c0];
                u[4+r] = g_U[ub + c1];
                size_t mb = (size_t)(b0+r)*(NS*NL*DD) + (size_t)slot*(NL*DD);
                oldv[r]   = memo[mb + c0];
                oldv[4+r] = memo[mb + c1];
            }
        }

        unsigned long long a0 = 0ull, a1 = 0ull, a2 = 0ull, a3 = 0ull;
        if (act) {
            const int kb = quarter * RQK;
            const ulonglong2* __restrict__ sp = (const ulonglong2*)(sumIn + kb);
            const float2* __restrict__ wsq = wst + (quarter*RSTK)*152 + p;
            #pragma unroll 4
            for (int kk = 0; kk < RSTK; kk++) {
                float2 w = wsq[kk*152];
                ulonglong2 s = sp[kk];
                unsigned long long wa = pk2(w.x, w.x), wb = pk2(w.y, w.y);
                a0 = fma2(s.x, wa, a0); a1 = fma2(s.y, wa, a1);
                a2 = fma2(s.x, wb, a2); a3 = fma2(s.y, wb, a3);
            }
            #pragma unroll 4
            for (int kk = RSTK; kk < RQK; kk++) {
                float2 w = *((const float2*)(Wr0 + (size_t)(kb+kk)*DD) + p);
                ulonglong2 s = sp[kk];
                unsigned long long wa = pk2(w.x, w.x), wb = pk2(w.y, w.y);
                a0 = fma2(s.x, wa, a0); a1 = fma2(s.y, wa, a1);
                a2 = fma2(s.x, wb, a2); a3 = fma2(s.y, wb, a3);
            }
        }
        if (quarter != 0 && act) {
            unsigned long long* pp_ = part + ((quarter-1)*RSLOT + p)*4;
            pp_[0] = a0; pp_[1] = a1; pp_[2] = a2; pp_[3] = a3;
        }
        __syncthreads();
        if (quarter == 0 && act) {
            #pragma unroll
            for (int qq = 0; qq < 3; qq++) {
                const unsigned long long* pp_ = part + (qq*RSLOT + p)*4;
                a0 = add2(a0, pp_[0]); a1 = add2(a1, pp_[1]);
                a2 = add2(a2, pp_[2]); a3 = add2(a3, pp_[3]);
            }
            float v[8];
            upk2(a0, v[0], v[1]); upk2(a1, v[2], v[3]);   // col0 rows 0..3
            upk2(a2, v[4], v[5]); upk2(a3, v[6], v[7]);   // col1 rows 0..3
            float h[8];
            #pragma unroll
            for (int i = 0; i < 8; i++) h[i] = tanhf(u[i] + v[i]*inv13);
            float4 si0 = sumIn[c0], si1 = sumIn[c1];
            sumOut[c0] = make_float4(si0.x + h[0]-oldv[0], si0.y + h[1]-oldv[1],
                                     si0.z + h[2]-oldv[2], si0.w + h[3]-oldv[3]);
            sumOut[c1] = make_float4(si1.x + h[4]-oldv[4], si1.y + h[5]-oldv[5],
                                     si1.z + h[6]-oldv[6], si1.w + h[7]-oldv[7]);
            #pragma unroll
            for (int r = 0; r < 4; r++) {
                size_t mb = (size_t)(b0+r)*(NS*NL*DD) + (size_t)slot*(NL*DD);
                memo[mb + c0] = h[r];
                memo[mb + c1] = h[4+r];
            }
        }
        slot++; if (slot == NS) slot = 0;
        __syncthreads();
    }
}

// ---------- epilogue gathers ----------
__global__ void k_gatherA(const float* __restrict__ memo) {
    int idx = blockIdx.x * blockDim.x + threadIdx.x;
    if (idx >= BB*KEP) return;
    int b = idx / KEP, k = idx % KEP;
    float v = 0.f;
    if (k < NS*DD)            { int s = k / DD, j = k % DD; v = memo[(size_t)b*(NS*NL*DD) + s*(NL*DD) + j]; }
    else if (k < NS*DD + DD)  { v = g_x0[b*DD + (k - NS*DD)]; }
    g_Aep[idx] = v;
}
__global__ void k_gatherW(const float* __restrict__ out_W, const float* __restrict__ skip_W) {
    int idx = blockIdx.x * blockDim.x + threadIdx.x;
    if (idx >= KEP*DIN) return;
    int k = idx / DIN, o = idx % DIN;
    float v = 0.f;
    if (k < NS*DD)            { int s = k / DD, j = k % DD; v = out_W[(s*(NL*DD) + j)*DIN + o]; }
    else if (k < NS*DD + DD)  { v = skip_W[(k - NS*DD)*DIN + o]; }
    g_Wep[idx] = v;
}

// ---------- epilogue GEMM (f32x2): 128x64 tile, 8x4 micro ----------
__global__ __launch_bounds__(256) void k_epigemm(const float* __restrict__ out_b,
                                                 const float* __restrict__ skip_b) {
    __shared__ float As[16*132];
    __shared__ float2 Bs2[16*64];
    int bn = blockIdx.x;   // 0..5
    int bm = blockIdx.y;   // 0..3
    int tid = threadIdx.x;
    int tr = tid >> 4, tc = tid & 15;
    int row0 = bm * 128, col0 = bn * 64;
    unsigned long long acc[4][4];
    #pragma unroll
    for (int i = 0; i < 4; i++)
        #pragma unroll
        for (int j = 0; j < 4; j++) acc[i][j] = 0ull;
    for (int k0 = 0; k0 < KEP; k0 += 16) {
        for (int i = tid; i < 128*16; i += 256) {
            int kk = i & 15, m = i >> 4;
            As[kk*132 + m] = g_Aep[(size_t)(row0+m)*KEP + k0 + kk];
        }
        for (int i = tid; i < 16*64; i += 256) {
            int n = i & 63, kk = i >> 6;
            float v = g_Wep[(k0+kk)*DIN + col0 + n];
            Bs2[kk*64 + n] = make_float2(v, v);
        }
        __syncthreads();
        #pragma unroll
        for (int kk = 0; kk < 16; kk++) {
            ulonglong2 aA = *(const ulonglong2*)&As[kk*132 + tr*8];
            ulonglong2 aB = *(const ulonglong2*)&As[kk*132 + tr*8 + 4];
            ulonglong2 bA = *(const ulonglong2*)&Bs2[kk*64 + tc*4];
            ulonglong2 bB = *(const ulonglong2*)&Bs2[kk*64 + tc*4 + 2];
            unsigned long long av[4] = {aA.x, aA.y, aB.x, aB.y};
            unsigned long long bv[4] = {bA.x, bA.y, bB.x, bB.y};
            #pragma unroll
            for (int i = 0; i < 4; i++)
                #pragma unroll
                for (int j = 0; j < 4; j++) acc[i][j] = fma2(av[i], bv[j], acc[i][j]);
        }
        __syncthreads();
    }
    #pragma unroll
    for (int i = 0; i < 4; i++) {
        int r0 = row0 + tr*8 + 2*i;
        #pragma unroll
        for (int j = 0; j < 4; j++) {
            int c = col0 + tc*4 + j;
            float v0, v1; upk2(acc[i][j], v0, v1);
            float bb = out_b[c] + skip_b[c];
            g_c[r0*DIN + c]     = v0 + bb;
            g_c[(r0+1)*DIN + c] = v1 + bb;
        }
    }
}

// ---------- LayerNorm ----------
__device__ __forceinline__ float blk_reduce(float v, float* sm) {
    int lane = threadIdx.x & 31, w = threadIdx.x >> 5;
    #pragma unroll
    for (int o = 16; o > 0; o >>= 1) v += __shfl_xor_sync(0xffffffff, v, o);
    if (lane == 0) sm[w] = v;
    __syncthreads();
    v = (threadIdx.x < 4) ? sm[threadIdx.x] : 0.f;
    if (threadIdx.x < 4) {
        #pragma unroll
        for (int o = 2; o > 0; o >>= 1) v += __shfl_xor_sync(0xf, v, o);
        if (threadIdx.x == 0) sm[0] = v;
    }
    __syncthreads();
    return sm[0];
}
__global__ __launch_bounds__(128) void k_ln(const float* __restrict__ g,
                                            const float* __restrict__ be,
                                            float* __restrict__ out) {
    __shared__ float sm[4];
    int b = blockIdx.x, tid = threadIdx.x;
    float v[3];
    float s = 0.f;
    #pragma unroll
    for (int r = 0; r < 3; r++) { v[r] = g_c[b*DIN + tid + r*128]; s += v[r]; }
    float mu = blk_reduce(s, sm) * (1.f / DIN);
    __syncthreads();
    float q = 0.f;
    #pragma unroll
    for (int r = 0; r < 3; r++) { float d = v[r] - mu; q += d * d; }
    float var = blk_reduce(q, sm) * (1.f / DIN);
    float rs = rsqrtf(var + EPSL);
    #pragma unroll
    for (int r = 0; r < 3; r++) {
        int i = tid + r*128;
        out[C_OFF + b*DIN + i] = (v[r] - mu) * rs * g[i] + be[i];
    }
}

// ---------- scoring head ----------
__global__ __launch_bounds__(64) void k_logit(const float* __restrict__ W1,
                                              const float* __restrict__ b1,
                                              const float* __restrict__ W2,
                                              const float* __restrict__ b2,
                                              float* __restrict__ out) {
    __shared__ float cs[DIN];
    __shared__ float red[2];
    int b = blockIdx.x, tid = threadIdx.x;
    for (int i = tid; i < DIN; i += 64) cs[i] = out[C_OFF + b*DIN + i];
    __syncthreads();
    float acc = b1[tid];
    for (int i = 0; i < DIN; i++) acc += cs[i] * W1[i*64 + tid];
    float r = fmaxf(acc, 0.f) * W2[tid];
    #pragma unroll
    for (int o = 16; o > 0; o >>= 1) r += __shfl_xor_sync(0xffffffff, r, o);
    if ((tid & 31) == 0) red[tid >> 5] = r;
    __syncthreads();
    if (tid == 0) out[LOGIT_OFF + b] = red[0] + red[1] + b2[0];
}

// ---------- launcher ----------
extern "C" void kernel_launch(void* const* d_in, const int* in_sizes, int n_in,
                              void* d_out, int out_size) {
    const float* we     = (const float*)d_in[0];
    const float* in_W   = (const float*)d_in[1];
    const float* in_b   = (const float*)d_in[2];
    const float* Wh     = (const float*)d_in[3];
    const float* Wr     = (const float*)d_in[4];
    const float* lb     = (const float*)d_in[5];
    const float* skip_W = (const float*)d_in[6];
    const float* skip_b = (const float*)d_in[7];
    const float* out_W  = (const float*)d_in[8];
    const float* out_b  = (const float*)d_in[9];
    const float* ln_g   = (const float*)d_in[10];
    const float* ln_b   = (const float*)d_in[11];
    const float* sh_W1  = (const float*)d_in[12];
    const float* sh_b1  = (const float*)d_in[13];
    const float* sh_W2  = (const float*)d_in[14];
    const float* sh_b2  = (const float*)d_in[15];
    float* out = (float*)d_out;
    float* memo = out + MEM_OFF;

    // smem: sum(2*304*16) + partial(3*160*4*8) + stash(4*40*152*8) = 219648 B
    const int rec_smem = 304*16*2 + 3*RSLOT*4*8 + 4*RSTK*152*8;
    cudaFuncSetAttribute(k_rec, cudaFuncAttributeMaxDynamicSharedMemorySize, rec_smem);

    // init output mem region (layers 1..7 stay zero; also ring "old" reads)
    k_zero_out<<<(MEM_SIZE + 255) / 256, 256>>>(memo, MEM_SIZE);

    // prep
    k_prep_M<<<DIN + 1, 128>>>(in_W, in_b, Wh, lb);
    k_x0<<<BB, 128>>>(we, in_W, in_b);

    // parallel input projection
    k_ugemm<<<dim3(5, 1024), 256>>>(we);

    // persistent recurrence
    k_rec<<<BB / 4, 640, rec_smem>>>(Wr, memo);

    // epilogue
    k_gatherA<<<(BB*KEP + 255) / 256, 256>>>(memo);
    k_gatherW<<<(KEP*DIN + 255) / 256, 256>>>(out_W, skip_W);
    k_epigemm<<<dim3(6, 4), 256>>>(out_b, skip_b);
    k_ln<<<BB, 128>>>(ln_g, ln_b, out);
    k_logit<<<BB, 64>>>(sh_W1, sh_b1, sh_W2, sh_b2, out);
}